// round 10
// baseline (speedup 1.0000x reference)
#include <cuda_runtime.h>
#include <cuda_fp16.h>
#include <cstdint>

// CapsuleLayer: conv(stride2,pad1, 32ic->512oc) via mma.sync fp16 2-term GEMM
// (A=fp16(x); B=1024*W split hi/lo fp16, both fp32-accum; epilogue /1024).
// PERSISTENT-B conv: CTA = 64 oc x whole image; B in SMEM once (92KB), A
// double-buffered per 128-px slab chunk. Cuts L2 traffic 756MB -> 377MB.
// Then 3 routing rounds (float4 reg-resident u, fused maxpool, ping-pong b).
// Shapes: x[8,8,32,64,64], W[512,32,3,3], bias[512] -> v[8,8,64,32,32] (fp32)

#define NB   8
#define T0_  8
#define Z0_  32
#define HIN  64
#define WIN  64
#define OC_  512
#define H1_  32
#define W1_  32
#define NPIX (H1_*W1_)      // 1024
#define KTOT 288            // 9 taps * 32 ic
#define NIMG 64
#define WSCALE 1024.0f
#define INV_WSCALE (1.0f/1024.0f)

// ---- device scratch ----
__device__ float  g_uhat[NB*NPIX*T0_*OC_];   // [n][hw][t0][oc]
__device__ float  g_v[NB*NPIX*OC_];          // [n][hw][t1*64+z]
__device__ __half g_xh[NIMG*HIN*WIN*Z0_];    // [img][h][w][ic]  fp16(x)
__device__ __half g_whi[OC_*KTOT];           // [oc][tap*32+ic]  fp16(1024W)
__device__ __half g_wlo[OC_*KTOT];           // residual
__device__ float  g_bA[NB*NPIX*64];          // routing logits after iter0
__device__ float  g_bB[NB*NPIX*64];          // routing logits after iter1

__device__ __forceinline__ uint32_t smem_u32(const void* p) {
    uint32_t a;
    asm("{ .reg .u64 t; cvta.to.shared.u64 t, %1; cvt.u32.u64 %0, t; }"
        : "=r"(a) : "l"(p));
    return a;
}
__device__ __forceinline__ void ldm_x4(uint32_t* r, uint32_t addr) {
    asm volatile("ldmatrix.sync.aligned.m8n8.x4.shared.b16 {%0,%1,%2,%3}, [%4];"
                 : "=r"(r[0]), "=r"(r[1]), "=r"(r[2]), "=r"(r[3]) : "r"(addr));
}
__device__ __forceinline__ void mma16816(float* d, const uint32_t* a,
                                         uint32_t b0, uint32_t b1) {
    asm volatile(
        "mma.sync.aligned.m16n8k16.row.col.f32.f16.f16.f32 "
        "{%0,%1,%2,%3}, {%4,%5,%6,%7}, {%8,%9}, {%0,%1,%2,%3};"
        : "+f"(d[0]), "+f"(d[1]), "+f"(d[2]), "+f"(d[3])
        : "r"(a[0]), "r"(a[1]), "r"(a[2]), "r"(a[3]), "r"(b0), "r"(b1));
}
__device__ __forceinline__ void cp16(uint32_t d, const void* s, uint32_t n) {
    asm volatile("cp.async.cg.shared.global [%0], [%1], 16, %2;"
                 :: "r"(d), "l"(s), "r"(n) : "memory");
}
__device__ __forceinline__ void cp_commit() {
    asm volatile("cp.async.commit_group;" ::: "memory");
}

// ========================= prep =============================================
__global__ __launch_bounds__(256) void xsplit_kernel(const float* __restrict__ x) {
    __shared__ float t[32][65];
    const int img = blockIdx.x;
    const int h   = blockIdx.y;
    const int tid = threadIdx.x;
    #pragma unroll
    for (int j = 0; j < 8; ++j) {
        int idx = tid + 256 * j;
        int ic = idx >> 6, w = idx & 63;
        t[ic][w] = x[((img * Z0_ + ic) * HIN + h) * WIN + w];
    }
    __syncthreads();
    #pragma unroll
    for (int j = 0; j < 8; ++j) {
        int idx = tid + 256 * j;
        int w = idx >> 5, ic = idx & 31;
        g_xh[((img * HIN + h) * WIN + w) * Z0_ + ic] = __float2half(t[ic][w]);
    }
}

__global__ void wsplit_kernel(const float* __restrict__ W) {
    int idx = blockIdx.x * 256 + threadIdx.x;
    if (idx >= OC_ * KTOT) return;
    int oc = idx / KTOT;
    int k  = idx - oc * KTOT;
    int tap = k >> 5, ic = k & 31;
    float v = W[oc * KTOT + ic * 9 + tap] * WSCALE;
    __half hi = __float2half(v);
    g_whi[idx] = hi;
    g_wlo[idx] = __float2half(v - __half2float(hi));
}

// ========================= conv: persistent-B mma.sync GEMM =================
// CTA = 64 oc x full image (1024 px). B (64oc x 9 chunks x hi/lo) resident in
// SMEM; A (128px x 64B) double-buffered per chunk. 8 warps = 4(m) x 2(n);
// warp tile = 32px x 32oc. Both split terms fp32-accum (R7-identical math).
#define APITCH 80
#define BCHUNK (64 * APITCH)           // 5120 B per (chunk, term)
#define BSTRIDE (2 * BCHUNK)           // 10240 B per chunk (hi+lo)
#define BBYTES (9 * BSTRIDE)           // 92160
#define ACHUNK (128 * APITCH)          // 10240
#define ABASE  BBYTES
#define SMEMTOT (BBYTES + 2 * ACHUNK)  // 112640

__global__ __launch_bounds__(256, 2) void conv_mma_kernel(
        const float* __restrict__ bias, int imgbase) {
    extern __shared__ char smem[];
    const uint32_t sb = smem_u32(smem);

    const int tid = threadIdx.x;
    const int lid = tid & 31;
    const int wid = tid >> 5;
    const int ocg = blockIdx.x;              // 0..7 (64-oc group)
    const int img = imgbase + blockIdx.y;

    const int warp_m = wid & 3;              // 4 warps over 128 px slab
    const int warp_n = wid >> 2;             // 2 warps over 64 oc
    const int wPx  = warp_m * 32;
    const int wOcL = warp_n * 32;

    const __half* xImg = g_xh + (size_t)img * (HIN * WIN * Z0_);

    // ---- load B once: 64 oc x 9 chunks x (hi,lo), 4608 cp16 ----
    #pragma unroll
    for (int k = 0; k < 18; ++k) {
        int f = tid + 256 * k;               // 0..4607
        int c    = f >> 9;                   // 512 cp16 per chunk
        int r9   = f & 511;
        int term = r9 >> 8;
        int row  = (r9 >> 2) & 63;
        int seg  = r9 & 3;
        const __half* src = (term ? g_wlo : g_whi)
            + (size_t)(ocg * 64 + row) * KTOT + c * 32 + seg * 8;
        uint32_t dst = sb + c * BSTRIDE + term * BCHUNK + row * APITCH + seg * 16;
        cp16(dst, src, 16u);
    }
    cp_commit();                             // group: B

    // ---- A staging: thread owns 32B (half row). r = tid>>1, half = tid&1 ----
    const int ar    = tid >> 1;
    const int ahalf = tid & 1;
    const uint32_t aDst = (uint32_t)(ar * APITCH + ahalf * 32);

    #define STAGE_A(s_, c_, buf_) do {                                        \
        int px = (s_) * 128 + ar;                                             \
        int oh = px >> 5, ow = px & 31;                                       \
        int kh = (c_) / 3, kw = (c_) - 3 * (kh);                              \
        int ih = 2 * oh - 1 + kh, iw = 2 * ow - 1 + kw;                       \
        bool valid = ((unsigned)ih < (unsigned)HIN) &&                        \
                     ((unsigned)iw < (unsigned)WIN);                          \
        uint32_t vb = valid ? 16u : 0u;                                       \
        const char* src = (const char*)(xImg +                                \
            (valid ? (size_t)(ih * WIN + iw) * Z0_ : 0)) + ahalf * 32;        \
        uint32_t d = sb + ABASE + (buf_) * ACHUNK + aDst;                     \
        cp16(d,      src,      vb);                                           \
        cp16(d + 16, src + 16, vb);                                           \
        cp_commit();                                                          \
    } while (0)

    STAGE_A(0, 0, 0);                        // group: A(g=0)

    // ldmatrix per-lane address components
    const uint32_t aRow  = ((lid >> 3) & 1) * 8 + (lid & 7);
    const uint32_t aKoff = (lid >> 4) * 16;
    const uint32_t aLane = (wPx + aRow) * APITCH + aKoff;
    const uint32_t bRow  = (lid >> 4) * 8 + (lid & 7);
    const uint32_t bKoff = ((lid >> 3) & 1) * 16;
    const uint32_t bLane = (wOcL + bRow) * APITCH + bKoff;

    float acc[2][4][4];
    #pragma unroll
    for (int i = 0; i < 2; ++i)
        #pragma unroll
        for (int j = 0; j < 4; ++j)
            #pragma unroll
            for (int q = 0; q < 4; ++q) acc[i][j][q] = 0.f;

    const int n = img >> 3, t0 = img & 7;
    int s_nxt = 0, c_nxt = 1;                // chunk index of g+1

    for (int g = 0; g < 72; ++g) {
        const int s = g / 9, c = g - 9 * s;  // (compiler strength-reduces)
        asm volatile("cp.async.wait_group 0;" ::: "memory");
        __syncthreads();
        if (g + 1 < 72)
            STAGE_A(s_nxt, c_nxt, (g + 1) & 1);
        if (++c_nxt == 9) { c_nxt = 0; ++s_nxt; }

        // ---- compute chunk c of slab s ----
        const uint32_t aB   = sb + ABASE + (g & 1) * ACHUNK;
        const uint32_t bHiB = sb + c * BSTRIDE;
        const uint32_t bLoB = bHiB + BCHUNK;
        #pragma unroll
        for (int ks = 0; ks < 2; ++ks) {
            uint32_t A[2][4];
            #pragma unroll
            for (int i = 0; i < 2; ++i)
                ldm_x4(A[i], aB + i * (16 * APITCH) + ks * 32 + aLane);
            #pragma unroll
            for (int jj = 0; jj < 2; ++jj) {
                uint32_t off = jj * (16 * APITCH) + ks * 32 + bLane;
                uint32_t Bhi[4], Blo[4];
                ldm_x4(Bhi, bHiB + off);
                ldm_x4(Blo, bLoB + off);
                #pragma unroll
                for (int i = 0; i < 2; ++i) {
                    mma16816(acc[i][2 * jj],     A[i], Bhi[0], Bhi[1]);
                    mma16816(acc[i][2 * jj + 1], A[i], Bhi[2], Bhi[3]);
                    mma16816(acc[i][2 * jj],     A[i], Blo[0], Blo[1]);
                    mma16816(acc[i][2 * jj + 1], A[i], Blo[2], Blo[3]);
                }
            }
        }

        if (c == 8) {
            // ---- epilogue for slab s: acc/1024 + bias -> u_hat; reset acc ----
            const int rowBase = s * 128 + wPx + (lid >> 2);
            const int ocBase  = ocg * 64 + wOcL + 2 * (lid & 3);
            #pragma unroll
            for (int j = 0; j < 4; ++j) {
                int oc = ocBase + j * 8;
                float2 bb = *(const float2*)(bias + oc);
                #pragma unroll
                for (int i = 0; i < 2; ++i) {
                    int r0 = rowBase + i * 16;
                    float* d0 = g_uhat +
                        ((size_t)((n * NPIX + r0) * T0_ + t0)) * OC_ + oc;
                    float* d1 = g_uhat +
                        ((size_t)((n * NPIX + r0 + 8) * T0_ + t0)) * OC_ + oc;
                    *(float2*)d0 = make_float2(acc[i][j][0] * INV_WSCALE + bb.x,
                                               acc[i][j][1] * INV_WSCALE + bb.y);
                    *(float2*)d1 = make_float2(acc[i][j][2] * INV_WSCALE + bb.x,
                                               acc[i][j][3] * INV_WSCALE + bb.y);
                    acc[i][j][0] = acc[i][j][1] = 0.f;
                    acc[i][j][2] = acc[i][j][3] = 0.f;
                }
            }
        }
    }
    #undef STAGE_A
}

// ========================= routing ==========================================
// One block per pixel. t1 = warp, q = z-quad, halfsel = t0 half; u as 4 float4.
// Ping-pong b: iter0 writes g_bA; iter1 reads g_bA writes g_bB; iter2 reads g_bB.
__global__ __launch_bounds__(256) void route_kernel(int iter) {
    __shared__ float sr[64];           // softmax routing weights
    __shared__ float sbp[64];          // pooled logits

    const int pix = blockIdx.x;
    const int n   = pix >> 10;
    const int hw  = pix & 1023;
    const int tid = threadIdx.x;
    const int t1   = tid >> 5;         // warp id = output capsule
    const int lane = tid & 31;
    const int q    = lane >> 1;        // z-quad 0..15
    const int halfsel = lane & 1;      // t0 in [0..3] or [4..7]
    const int t0b  = halfsel * 4;

    const float* bin = (iter == 1) ? g_bA : g_bB;   // pool source (iter>0)
    float*       bout = (iter == 0) ? g_bA : g_bB;  // agreement target (iter<2)

    const float* up = g_uhat + (size_t)pix * 4096;
    float4 U[4];
    #pragma unroll
    for (int i = 0; i < 4; ++i)
        U[i] = *(const float4*)(up + ((t0b + i) * 8 + t1) * 64 + q * 4);

    if (iter > 0) {
        if (tid < 64) {    // fused 3x3 maxpool over spatial neighbors (read-only)
            int h = hw >> 5, ww = hw & 31;
            float m = -3.402823466e38f;
            #pragma unroll
            for (int dh = -1; dh <= 1; ++dh) {
                int hh = h + dh;
                if ((unsigned)hh >= (unsigned)H1_) continue;
                #pragma unroll
                for (int dw = -1; dw <= 1; ++dw) {
                    int w2 = ww + dw;
                    if ((unsigned)w2 >= (unsigned)W1_) continue;
                    m = fmaxf(m, bin[((size_t)n * NPIX + hh * W1_ + w2) * 64 + tid]);
                }
            }
            sbp[tid] = m;
        }
        __syncthreads();
        if (tid < 8) {     // softmax over t1 for t0 = tid
            float m = -1e30f;
            #pragma unroll
            for (int t = 0; t < 8; ++t) m = fmaxf(m, sbp[tid * 8 + t]);
            float e[8], s = 0.f;
            #pragma unroll
            for (int t = 0; t < 8; ++t) { e[t] = expf(sbp[tid * 8 + t] - m); s += e[t]; }
            float inv = 1.f / s;
            #pragma unroll
            for (int t = 0; t < 8; ++t) sr[tid * 8 + t] = e[t] * inv;
        }
        __syncthreads();
    }

    // p for the 4 owned z values (half-sum over 4 t0 + partner shuffle)
    float p4[4];
    if (iter > 0) {
        float r[4];
        #pragma unroll
        for (int i = 0; i < 4; ++i) r[i] = sr[(t0b + i) * 8 + t1];
        #pragma unroll
        for (int j = 0; j < 4; ++j)
            p4[j] = r[0] * (&U[0].x)[j] + r[1] * (&U[1].x)[j]
                  + r[2] * (&U[2].x)[j] + r[3] * (&U[3].x)[j];
    } else {
        #pragma unroll
        for (int j = 0; j < 4; ++j)
            p4[j] = 0.125f * ((&U[0].x)[j] + (&U[1].x)[j]
                            + (&U[2].x)[j] + (&U[3].x)[j]);
    }
    #pragma unroll
    for (int j = 0; j < 4; ++j)
        p4[j] += __shfl_xor_sync(0xffffffffu, p4[j], 1);

    // squared norm for this t1: warp sum (each quad present on 2 lanes -> x0.5)
    float s2 = p4[0] * p4[0] + p4[1] * p4[1] + p4[2] * p4[2] + p4[3] * p4[3];
    #pragma unroll
    for (int off = 16; off; off >>= 1)
        s2 += __shfl_xor_sync(0xffffffffu, s2, off);
    float nn = 0.5f * s2;
    float f = nn / ((1.f + nn) * sqrtf(nn + 1e-9f));

    float v4[4];
    #pragma unroll
    for (int j = 0; j < 4; ++j) v4[j] = p4[j] * f;

    if (iter == 2) {      // coalesced pixel-major scratch; transposed later
        if (halfsel == 0)
            *(float4*)(g_v + (size_t)pix * OC_ + t1 * 64 + q * 4) =
                make_float4(v4[0], v4[1], v4[2], v4[3]);
        return;
    }

    // agreement: bout[t0][t1] = bin_cum + sum_z u*v (thread has u 4t0 x 4z, v 4z)
    float da[4];
    #pragma unroll
    for (int i = 0; i < 4; ++i)
        da[i] = (&U[i].x)[0] * v4[0] + (&U[i].x)[1] * v4[1]
              + (&U[i].x)[2] * v4[2] + (&U[i].x)[3] * v4[3];
    #pragma unroll
    for (int off = 2; off <= 16; off <<= 1)
        #pragma unroll
        for (int i = 0; i < 4; ++i)
            da[i] += __shfl_xor_sync(0xffffffffu, da[i], off);

    if (lane < 2) {       // lane0: t0=0..3, lane1: t0=4..7
        const float* bcum = g_bA + ((size_t)n * NPIX + hw) * 64;
        float* bo = bout + ((size_t)n * NPIX + hw) * 64;
        #pragma unroll
        for (int i = 0; i < 4; ++i) {
            int c = (t0b + i) * 8 + t1;
            float bold = (iter == 0) ? 0.f : bcum[c];
            bo[c] = bold + da[i];
        }
    }
}

// ---- transpose g_v [n][hw][c] -> out [n][c][hw] ----
__global__ __launch_bounds__(256) void vtrans_kernel(float* __restrict__ out) {
    __shared__ float t[32][33];
    const int n   = blockIdx.z;
    const int hw0 = blockIdx.x * 32;
    const int c0  = blockIdx.y * 32;
    const int x = threadIdx.x & 31, y = threadIdx.x >> 5;
    #pragma unroll
    for (int yy = y; yy < 32; yy += 8)
        t[yy][x] = g_v[((size_t)n * NPIX + hw0 + yy) * OC_ + c0 + x];
    __syncthreads();
    #pragma unroll
    for (int yy = y; yy < 32; yy += 8)
        out[((size_t)n * OC_ + c0 + yy) * NPIX + hw0 + x] = t[x][yy];
}

extern "C" void kernel_launch(void* const* d_in, const int* in_sizes, int n_in,
                              void* d_out, int out_size) {
    const float* x    = (const float*)d_in[0];
    const float* W    = (const float*)d_in[1];
    const float* bias = (const float*)d_in[2];
    float* out = (float*)d_out;

    cudaFuncSetAttribute(conv_mma_kernel,
                         cudaFuncAttributeMaxDynamicSharedMemorySize, SMEMTOT);

    xsplit_kernel<<<dim3(NIMG, HIN), 256>>>(x);
    wsplit_kernel<<<(OC_ * KTOT + 255) / 256, 256>>>(W);
    // 4 img-slices (6th launch overall = conv, so ncu -s 5 -c 1 captures conv)
    conv_mma_kernel<<<dim3(8, 16), 256, SMEMTOT>>>(bias, 0);
    conv_mma_kernel<<<dim3(8, 16), 256, SMEMTOT>>>(bias, 16);
    conv_mma_kernel<<<dim3(8, 16), 256, SMEMTOT>>>(bias, 32);
    conv_mma_kernel<<<dim3(8, 16), 256, SMEMTOT>>>(bias, 48);
    route_kernel<<<NB * NPIX, 256>>>(0);
    route_kernel<<<NB * NPIX, 256>>>(1);
    route_kernel<<<NB * NPIX, 256>>>(2);
    vtrans_kernel<<<dim3(32, 16, NB), 256>>>(out);
}

// round 11
// speedup vs baseline: 1.2983x; 1.2983x over previous
#include <cuda_runtime.h>
#include <cuda_fp16.h>
#include <cstdint>

// CapsuleLayer: conv(stride2,pad1, 32ic->512oc) per (n,t0) image via mma.sync
// fp16 2-term implicit GEMM (A=fp16(x); B=1024*W split hi/lo fp16, epilogue /1024),
// R5-measured-best conv pipeline (double-buffer cp.async, 2-sync). Then 3 routing
// rounds (float4 register-resident u, fused 3x3 maxpool, ping-pong b buffers).
// Shapes: x[8,8,32,64,64], W[512,32,3,3], bias[512] -> v[8,8,64,32,32] (fp32)

#define NB   8
#define T0_  8
#define Z0_  32
#define HIN  64
#define WIN  64
#define OC_  512
#define H1_  32
#define W1_  32
#define NPIX (H1_*W1_)      // 1024
#define KTOT 288            // 9 taps * 32 ic
#define NIMG 64
#define WSCALE 1024.0f
#define INV_WSCALE (1.0f/1024.0f)

// ---- device scratch ----
__device__ float  g_uhat[NB*NPIX*T0_*OC_];   // [n][hw][t0][oc]
__device__ float  g_v[NB*NPIX*OC_];          // [n][hw][t1*64+z]
__device__ __half g_xh[NIMG*HIN*WIN*Z0_];    // [img][h][w][ic]  fp16(x)
__device__ __half g_whi[OC_*KTOT];           // [oc][tap*32+ic]  fp16(1024W)
__device__ __half g_wlo[OC_*KTOT];           // residual
__device__ float  g_bA[NB*NPIX*64];          // routing logits after iter0
__device__ float  g_bB[NB*NPIX*64];          // routing logits after iter1

__device__ __forceinline__ uint32_t smem_u32(const void* p) {
    uint32_t a;
    asm("{ .reg .u64 t; cvta.to.shared.u64 t, %1; cvt.u32.u64 %0, t; }"
        : "=r"(a) : "l"(p));
    return a;
}
__device__ __forceinline__ void ldm_x4(uint32_t* r, uint32_t addr) {
    asm volatile("ldmatrix.sync.aligned.m8n8.x4.shared.b16 {%0,%1,%2,%3}, [%4];"
                 : "=r"(r[0]), "=r"(r[1]), "=r"(r[2]), "=r"(r[3]) : "r"(addr));
}
__device__ __forceinline__ void mma16816(float* d, const uint32_t* a,
                                         uint32_t b0, uint32_t b1) {
    asm volatile(
        "mma.sync.aligned.m16n8k16.row.col.f32.f16.f16.f32 "
        "{%0,%1,%2,%3}, {%4,%5,%6,%7}, {%8,%9}, {%0,%1,%2,%3};"
        : "+f"(d[0]), "+f"(d[1]), "+f"(d[2]), "+f"(d[3])
        : "r"(a[0]), "r"(a[1]), "r"(a[2]), "r"(a[3]), "r"(b0), "r"(b1));
}
__device__ __forceinline__ void cp16(uint32_t d, const void* s, uint32_t n) {
    asm volatile("cp.async.cg.shared.global [%0], [%1], 16, %2;"
                 :: "r"(d), "l"(s), "r"(n) : "memory");
}
__device__ __forceinline__ void cp_commit() {
    asm volatile("cp.async.commit_group;" ::: "memory");
}

// ========================= prep =============================================
__global__ __launch_bounds__(256) void xsplit_kernel(const float* __restrict__ x) {
    __shared__ float t[32][65];
    const int img = blockIdx.x;
    const int h   = blockIdx.y;
    const int tid = threadIdx.x;
    #pragma unroll
    for (int j = 0; j < 8; ++j) {
        int idx = tid + 256 * j;
        int ic = idx >> 6, w = idx & 63;
        t[ic][w] = x[((img * Z0_ + ic) * HIN + h) * WIN + w];
    }
    __syncthreads();
    #pragma unroll
    for (int j = 0; j < 8; ++j) {
        int idx = tid + 256 * j;
        int w = idx >> 5, ic = idx & 31;
        g_xh[((img * HIN + h) * WIN + w) * Z0_ + ic] = __float2half(t[ic][w]);
    }
}

__global__ void wsplit_kernel(const float* __restrict__ W) {
    int idx = blockIdx.x * 256 + threadIdx.x;
    if (idx >= OC_ * KTOT) return;
    int oc = idx / KTOT;
    int k  = idx - oc * KTOT;
    int tap = k >> 5, ic = k & 31;
    float v = W[oc * KTOT + ic * 9 + tap] * WSCALE;
    __half hi = __float2half(v);
    g_whi[idx] = hi;
    g_wlo[idx] = __float2half(v - __half2float(hi));
}

// ========================= conv: mma.sync implicit GEMM (R5 pipeline) =======
// CTA = 128 px x 128 oc of one image; 8 warps = 4(m) x 2(n); warp = 32px x 64oc.
// K = 9 chunks of 32 (1 tap x 32 ic), cp.async double-buffered, 2 syncs/chunk.
#define APITCH  80
#define OPBYTES (128 * APITCH)     // 10240 per operand
#define STGB    (3 * OPBYTES)      // A, Bhi, Blo = 30720
#define SMEMTOT (2 * STGB)         // 61440

__device__ __forceinline__ void stage_chunk(
        int c, uint32_t sbase, uint32_t dA, int oh, int ow,
        const __half* xImg, const __half* wH, const __half* wL) {
    int kh = c / 3, kw = c - 3 * kh;
    int ih = 2 * oh - 1 + kh, iw = 2 * ow - 1 + kw;
    bool valid = ((unsigned)ih < (unsigned)HIN) && ((unsigned)iw < (unsigned)WIN);
    uint32_t vb = valid ? 16u : 0u;
    size_t so = valid ? (size_t)(ih * WIN + iw) * Z0_ : 0;
    const char* aH = (const char*)(xImg + so);
    cp16(sbase + dA,      aH,      vb);
    cp16(sbase + dA + 16, aH + 16, vb);
    const char* bH = (const char*)(wH + c * 32);
    const char* bL = (const char*)(wL + c * 32);
    cp16(sbase + OPBYTES + dA,          bH,      16u);
    cp16(sbase + OPBYTES + dA + 16,     bH + 16, 16u);
    cp16(sbase + 2 * OPBYTES + dA,      bL,      16u);
    cp16(sbase + 2 * OPBYTES + dA + 16, bL + 16, 16u);
    cp_commit();
}

__device__ __forceinline__ void compute_chunk(
        uint32_t sbase, uint32_t aLane, uint32_t bLane, float acc[2][8][4]) {
    const uint32_t aB   = sbase;
    const uint32_t bHiB = sbase + OPBYTES;
    const uint32_t bLoB = sbase + 2 * OPBYTES;
    #pragma unroll
    for (int ks = 0; ks < 2; ++ks) {
        uint32_t A[2][4];
        #pragma unroll
        for (int i = 0; i < 2; ++i)
            ldm_x4(A[i], aB + i * (16 * APITCH) + ks * 32 + aLane);
        #pragma unroll
        for (int j = 0; j < 4; ++j) {
            uint32_t off = j * (16 * APITCH) + ks * 32 + bLane;
            uint32_t Bhi[4], Blo[4];
            ldm_x4(Bhi, bHiB + off);
            ldm_x4(Blo, bLoB + off);
            #pragma unroll
            for (int i = 0; i < 2; ++i) {
                mma16816(acc[i][2 * j],     A[i], Bhi[0], Bhi[1]);
                mma16816(acc[i][2 * j + 1], A[i], Bhi[2], Bhi[3]);
                mma16816(acc[i][2 * j],     A[i], Blo[0], Blo[1]);
                mma16816(acc[i][2 * j + 1], A[i], Blo[2], Blo[3]);
            }
        }
    }
}

__global__ __launch_bounds__(256, 2) void conv_mma_kernel(const float* __restrict__ bias) {
    extern __shared__ char smem[];
    const uint32_t base0 = smem_u32(smem);
    const uint32_t base1 = base0 + STGB;

    const int tid  = threadIdx.x;
    const int lid  = tid & 31;
    const int wid  = tid >> 5;
    const int mblk = blockIdx.x;   // 0..7 (128-pixel slab)
    const int nblk = blockIdx.y;   // 0..3 (128-oc slab)
    const int img  = blockIdx.z;   // 0..63

    const int warp_m = wid & 3;
    const int warp_n = wid >> 2;
    const int wPx = warp_m * 32;
    const int wOc = warp_n * 64;

    const int p_loc = tid >> 1;
    const int half  = tid & 1;
    const int p     = mblk * 128 + p_loc;
    const int oh = p >> 5, ow = p & 31;
    const uint32_t dA = (uint32_t)(p_loc * APITCH + half * 32);
    const __half* xImg = g_xh + (size_t)img * (HIN * WIN * Z0_) + half * 16;
    const __half* wH = g_whi + (size_t)(nblk * 128 + p_loc) * KTOT + half * 16;
    const __half* wL = g_wlo + (size_t)(nblk * 128 + p_loc) * KTOT + half * 16;

    const uint32_t aRow  = ((lid >> 3) & 1) * 8 + (lid & 7);
    const uint32_t aKoff = (lid >> 4) * 16;
    const uint32_t aLane = (wPx + aRow) * APITCH + aKoff;
    const uint32_t bRow  = (lid >> 4) * 8 + (lid & 7);
    const uint32_t bKoff = ((lid >> 3) & 1) * 16;
    const uint32_t bLane = (wOc + bRow) * APITCH + bKoff;

    float acc[2][8][4];
    #pragma unroll
    for (int i = 0; i < 2; ++i)
        #pragma unroll
        for (int j = 0; j < 8; ++j)
            #pragma unroll
            for (int q = 0; q < 4; ++q) acc[i][j][q] = 0.f;

    stage_chunk(0, base0, dA, oh, ow, xImg, wH, wL);
    stage_chunk(1, base1, dA, oh, ow, xImg, wH, wL);

    #pragma unroll
    for (int c = 0; c < 9; ++c) {
        if (c < 8) asm volatile("cp.async.wait_group 1;" ::: "memory");
        else       asm volatile("cp.async.wait_group 0;" ::: "memory");
        __syncthreads();
        compute_chunk((c & 1) ? base1 : base0, aLane, bLane, acc);
        if (c + 2 < 9) {
            __syncthreads();
            stage_chunk(c + 2, (c & 1) ? base1 : base0, dA, oh, ow, xImg, wH, wL);
        }
    }

    // ---- epilogue: acc/1024 + bias, write pixel-major u_hat ----
    const int n = img >> 3, t0 = img & 7;
    const int rowBase = mblk * 128 + wPx + (lid >> 2);
    const int ocBase  = nblk * 128 + wOc + 2 * (lid & 3);
    #pragma unroll
    for (int j = 0; j < 8; ++j) {
        int oc = ocBase + j * 8;
        float2 bb = *(const float2*)(bias + oc);
        #pragma unroll
        for (int i = 0; i < 2; ++i) {
            int r0 = rowBase + i * 16;
            float* d0 = g_uhat + ((size_t)((n * NPIX + r0) * T0_ + t0)) * OC_ + oc;
            float* d1 = g_uhat + ((size_t)((n * NPIX + r0 + 8) * T0_ + t0)) * OC_ + oc;
            *(float2*)d0 = make_float2(acc[i][j][0] * INV_WSCALE + bb.x,
                                       acc[i][j][1] * INV_WSCALE + bb.y);
            *(float2*)d1 = make_float2(acc[i][j][2] * INV_WSCALE + bb.x,
                                       acc[i][j][3] * INV_WSCALE + bb.y);
        }
    }
}

// ========================= routing ==========================================
// One block per pixel. t1 = warp, q = z-quad, halfsel = t0 half; u as 4 float4.
// Ping-pong b: iter0 writes g_bA; iter1 reads g_bA writes g_bB; iter2 reads g_bB.
__global__ __launch_bounds__(256) void route_kernel(int iter) {
    __shared__ float sr[64];           // softmax routing weights
    __shared__ float sbp[64];          // pooled logits

    const int pix = blockIdx.x;
    const int n   = pix >> 10;
    const int hw  = pix & 1023;
    const int tid = threadIdx.x;
    const int t1   = tid >> 5;         // warp id = output capsule
    const int lane = tid & 31;
    const int q    = lane >> 1;        // z-quad 0..15
    const int halfsel = lane & 1;      // t0 in [0..3] or [4..7]
    const int t0b  = halfsel * 4;

    const float* bin = (iter == 1) ? g_bA : g_bB;   // pool source (iter>0)
    float*       bout = (iter == 0) ? g_bA : g_bB;  // agreement target (iter<2)

    const float* up = g_uhat + (size_t)pix * 4096;
    float4 U[4];
    #pragma unroll
    for (int i = 0; i < 4; ++i)
        U[i] = *(const float4*)(up + ((t0b + i) * 8 + t1) * 64 + q * 4);

    if (iter > 0) {
        if (tid < 64) {    // fused 3x3 maxpool over spatial neighbors (read-only)
            int h = hw >> 5, ww = hw & 31;
            float m = -3.402823466e38f;
            #pragma unroll
            for (int dh = -1; dh <= 1; ++dh) {
                int hh = h + dh;
                if ((unsigned)hh >= (unsigned)H1_) continue;
                #pragma unroll
                for (int dw = -1; dw <= 1; ++dw) {
                    int w2 = ww + dw;
                    if ((unsigned)w2 >= (unsigned)W1_) continue;
                    m = fmaxf(m, bin[((size_t)n * NPIX + hh * W1_ + w2) * 64 + tid]);
                }
            }
            sbp[tid] = m;
        }
        __syncthreads();
        if (tid < 8) {     // softmax over t1 for t0 = tid
            float m = -1e30f;
            #pragma unroll
            for (int t = 0; t < 8; ++t) m = fmaxf(m, sbp[tid * 8 + t]);
            float e[8], s = 0.f;
            #pragma unroll
            for (int t = 0; t < 8; ++t) { e[t] = expf(sbp[tid * 8 + t] - m); s += e[t]; }
            float inv = 1.f / s;
            #pragma unroll
            for (int t = 0; t < 8; ++t) sr[tid * 8 + t] = e[t] * inv;
        }
        __syncthreads();
    }

    // p for the 4 owned z values (half-sum over 4 t0 + partner shuffle)
    float p4[4];
    if (iter > 0) {
        float r[4];
        #pragma unroll
        for (int i = 0; i < 4; ++i) r[i] = sr[(t0b + i) * 8 + t1];
        #pragma unroll
        for (int j = 0; j < 4; ++j)
            p4[j] = r[0] * (&U[0].x)[j] + r[1] * (&U[1].x)[j]
                  + r[2] * (&U[2].x)[j] + r[3] * (&U[3].x)[j];
    } else {
        #pragma unroll
        for (int j = 0; j < 4; ++j)
            p4[j] = 0.125f * ((&U[0].x)[j] + (&U[1].x)[j]
                            + (&U[2].x)[j] + (&U[3].x)[j]);
    }
    #pragma unroll
    for (int j = 0; j < 4; ++j)
        p4[j] += __shfl_xor_sync(0xffffffffu, p4[j], 1);

    // squared norm for this t1: warp sum (each quad present on 2 lanes -> x0.5)
    float s2 = p4[0] * p4[0] + p4[1] * p4[1] + p4[2] * p4[2] + p4[3] * p4[3];
    #pragma unroll
    for (int off = 16; off; off >>= 1)
        s2 += __shfl_xor_sync(0xffffffffu, s2, off);
    float nn = 0.5f * s2;
    float f = nn / ((1.f + nn) * sqrtf(nn + 1e-9f));

    float v4[4];
    #pragma unroll
    for (int j = 0; j < 4; ++j) v4[j] = p4[j] * f;

    if (iter == 2) {      // coalesced pixel-major scratch; transposed later
        if (halfsel == 0)
            *(float4*)(g_v + (size_t)pix * OC_ + t1 * 64 + q * 4) =
                make_float4(v4[0], v4[1], v4[2], v4[3]);
        return;
    }

    // agreement: bout[t0][t1] = bin_cum + sum_z u*v (thread has u 4t0 x 4z, v 4z)
    float da[4];
    #pragma unroll
    for (int i = 0; i < 4; ++i)
        da[i] = (&U[i].x)[0] * v4[0] + (&U[i].x)[1] * v4[1]
              + (&U[i].x)[2] * v4[2] + (&U[i].x)[3] * v4[3];
    #pragma unroll
    for (int off = 2; off <= 16; off <<= 1)
        #pragma unroll
        for (int i = 0; i < 4; ++i)
            da[i] += __shfl_xor_sync(0xffffffffu, da[i], off);

    if (lane < 2) {       // lane0: t0=0..3, lane1: t0=4..7
        const float* bcum = g_bA + ((size_t)n * NPIX + hw) * 64;
        float* bo = bout + ((size_t)n * NPIX + hw) * 64;
        #pragma unroll
        for (int i = 0; i < 4; ++i) {
            int c = (t0b + i) * 8 + t1;
            float bold = (iter == 0) ? 0.f : bcum[c];
            bo[c] = bold + da[i];
        }
    }
}

// ---- transpose g_v [n][hw][c] -> out [n][c][hw] ----
__global__ __launch_bounds__(256) void vtrans_kernel(float* __restrict__ out) {
    __shared__ float t[32][33];
    const int n   = blockIdx.z;
    const int hw0 = blockIdx.x * 32;
    const int c0  = blockIdx.y * 32;
    const int x = threadIdx.x & 31, y = threadIdx.x >> 5;
    #pragma unroll
    for (int yy = y; yy < 32; yy += 8)
        t[yy][x] = g_v[((size_t)n * NPIX + hw0 + yy) * OC_ + c0 + x];
    __syncthreads();
    #pragma unroll
    for (int yy = y; yy < 32; yy += 8)
        out[((size_t)n * OC_ + c0 + yy) * NPIX + hw0 + x] = t[x][yy];
}

extern "C" void kernel_launch(void* const* d_in, const int* in_sizes, int n_in,
                              void* d_out, int out_size) {
    const float* x    = (const float*)d_in[0];
    const float* W    = (const float*)d_in[1];
    const float* bias = (const float*)d_in[2];
    float* out = (float*)d_out;

    cudaFuncSetAttribute(conv_mma_kernel,
                         cudaFuncAttributeMaxDynamicSharedMemorySize, SMEMTOT);

    xsplit_kernel<<<dim3(NIMG, HIN), 256>>>(x);
    wsplit_kernel<<<(OC_ * KTOT + 255) / 256, 256>>>(W);
    conv_mma_kernel<<<dim3(8, 4, NIMG), 256, SMEMTOT>>>(bias);
    route_kernel<<<NB * NPIX, 256>>>(0);
    route_kernel<<<NB * NPIX, 256>>>(1);
    route_kernel<<<NB * NPIX, 256>>>(2);
    vtrans_kernel<<<dim3(32, 16, NB), 256>>>(out);
}